// round 9
// baseline (speedup 1.0000x reference)
#include <cuda_runtime.h>
#include <cstdint>

#define T_ 128
#define B_ 32
#define I_ 128
#define H_ 320
#define O_ 32
#define G_ 8
#define HP 80            // hidden rows per CTA (H/4)
#define NTHR 256
#define NW 8             // warps per CTA
#define RPW 10           // rows per warp
#define AX 0.2f
#define AW 0.1f
#define KW 0.9f
#define SIGNB 256
#define EA_STRIDE 260

__device__ __forceinline__ uint32_t smem_u32(const void* p) {
    return (uint32_t)__cvta_generic_to_shared(p);
}
__device__ __forceinline__ void st_cluster_f32(uint32_t addr, uint32_t peer, float v) {
    uint32_t ra;
    asm volatile("mapa.shared::cluster.u32 %0, %1, %2;" : "=r"(ra) : "r"(addr), "r"(peer));
    asm volatile("st.shared::cluster.f32 [%0], %1;" :: "r"(ra), "f"(v) : "memory");
}
#define CLUSTER_SYNC() do { \
    asm volatile("barrier.cluster.arrive.aligned;" ::: "memory"); \
    asm volatile("barrier.cluster.wait.aligned;"   ::: "memory"); } while (0)

// EXACT R3 arithmetic helpers (do not reassociate)
__device__ __forceinline__ float dot4r(float4 w, float4 v) {
    return fmaxf(w.x, 0.f) * v.x + fmaxf(w.y, 0.f) * v.y +
           fmaxf(w.z, 0.f) * v.z + fmaxf(w.w, 0.f) * v.w;
}
__device__ __forceinline__ float4 upd4(float4 w, float no, float4 a, float4 bq) {
    float4 r;
    r.x = fmaf(w.x, KW, fmaf(no, bq.x, a.x));
    r.y = fmaf(w.y, KW, fmaf(no, bq.y, a.y));
    r.z = fmaf(w.z, KW, fmaf(no, bq.z, a.z));
    r.w = fmaf(w.w, KW, fmaf(no, bq.w, a.w));
    return r;
}

__global__ void __launch_bounds__(NTHR, 1)
rnn_kernel(const float* __restrict__ x, const float* __restrict__ Rs,
           const float* __restrict__ W_x2h, const float* __restrict__ W_h2h,
           const float* __restrict__ b_h2h, const float* __restrict__ W_attn,
           const float* __restrict__ b_attn, const float* __restrict__ c_plas,
           float* __restrict__ hs)
{
    __shared__ float s_buf[2][H_];          // output double buffer
    __shared__ float s_ea[G_ * EA_STRIDE];  // relu(W_attn), cols<256
    __shared__ float s_xm[I_];
    __shared__ float s_bh[HP];
    __shared__ float s_st[HP];
    __shared__ float s_wd[HP];              // shadow diagonal (bitwise == in-array diag)

    const int tid  = threadIdx.x;
    const int lane = tid & 31;
    const int wid  = tid >> 5;
    uint32_t rank; asm("mov.u32 %0, %%cluster_ctarank;" : "=r"(rank));
    const int b  = blockIdx.x >> 2;
    const int r0 = (int)rank * HP;

    // ---------------- init SMEM (FIX: cover all H_=320 entries at NTHR=256) ----
    for (int f = tid; f < H_; f += NTHR) { s_buf[0][f] = 0.f; s_buf[1][f] = 0.f; }
    for (int k = 0; k < 8; k++) {           // ea cols 0..255 (mask_a zero beyond)
        int f = tid + k * NTHR;
        int g = f >> 8, c = f & 255;
        s_ea[g * EA_STRIDE + c] = fmaxf(W_attn[g * H_ + c], 0.f);
    }
    if (tid < HP) {
        s_bh[tid] = b_h2h[r0 + tid];
        s_st[tid] = 0.f;
        s_wd[tid] = 0.f;
    }

    // per-thread constants (R3 expressions)
    const float cb0 = fabsf(__ldg(&c_plas[0]));
    const float cb1 = fabsf(__ldg(&c_plas[1]));
    const float cb2 = fabsf(__ldg(&c_plas[2]));
    const float cb3 = fabsf(__ldg(&c_plas[3]));
    const float cb4 = fabsf(__ldg(&c_plas[4]));
    const float cb5 = fabsf(__ldg(&c_plas[5]));
    const float ba_r = __ldg(&b_attn[lane & 7]);

    // ---------------- register-resident plastic weights (R3 column ownership) ----
    // lane l owns: wx cols [4l,4l+4); wh cols [4l,4l+4), [4(l+32),..), l<16: [4(l+64),..)
    float4 wx_r[RPW], wh0_r[RPW], wh1_r[RPW], wh2_r[RPW];
    #pragma unroll
    for (int rr = 0; rr < RPW; rr++) {
        int rg = r0 + wid * RPW + rr;
        float4 w = *(const float4*)(W_x2h + rg * I_ + 4 * lane);
        wx_r[rr] = make_float4(fmaxf(w.x, 0.f), fmaxf(w.y, 0.f),
                               fmaxf(w.z, 0.f), fmaxf(w.w, 0.f));
        // segment 0: cols 4l..4l+3  (sign +1)
        {
            int c0 = 4 * lane;
            float4 h = *(const float4*)(W_h2h + rg * H_ + c0);
            float4 v = make_float4(fmaxf(h.x, 0.f), fmaxf(h.y, 0.f),
                                   fmaxf(h.z, 0.f), fmaxf(h.w, 0.f));
            if (c0     == rg) v.x = 0.f;
            if (c0 + 1 == rg) v.y = 0.f;
            if (c0 + 2 == rg) v.z = 0.f;
            if (c0 + 3 == rg) v.w = 0.f;
            wh0_r[rr] = v;
        }
        // segment 1: cols 4(l+32)..  (sign +1)
        {
            int c0 = 4 * (lane + 32);
            float4 h = *(const float4*)(W_h2h + rg * H_ + c0);
            float4 v = make_float4(fmaxf(h.x, 0.f), fmaxf(h.y, 0.f),
                                   fmaxf(h.z, 0.f), fmaxf(h.w, 0.f));
            if (c0     == rg) v.x = 0.f;
            if (c0 + 1 == rg) v.y = 0.f;
            if (c0 + 2 == rg) v.z = 0.f;
            if (c0 + 3 == rg) v.w = 0.f;
            wh1_r[rr] = v;
        }
        // segment 2 (lane<16): cols 4(l+64).. >= 256 (sign -1, stored negated)
        wh2_r[rr] = make_float4(0, 0, 0, 0);
        if (lane < 16) {
            int c0 = 4 * (lane + 64);
            float4 h = *(const float4*)(W_h2h + rg * H_ + c0);
            float4 v = make_float4(-fmaxf(h.x, 0.f), -fmaxf(h.y, 0.f),
                                   -fmaxf(h.z, 0.f), -fmaxf(h.w, 0.f));
            if (c0     == rg) v.x = 0.f;
            if (c0 + 1 == rg) v.y = 0.f;
            if (c0 + 2 == rg) v.z = 0.f;
            if (c0 + 3 == rg) v.w = 0.f;
            wh2_r[rr] = v;
        }
    }

    __syncthreads();
    CLUSTER_SYNC();

    // ---------------- time loop ----------------
    for (int t = 0; t < T_; t++) {
        const float* bold = s_buf[t & 1];
        float*       bnew = s_buf[(t + 1) & 1];
        const float rcur = __ldg(&Rs[t * B_ + b]);
        const float awR  = AW * rcur;

        // ---- phase A': warp0 = attention logits + softmax + xm (R3 verbatim) ----
        if (wid == 0) {
            float4 xr4 = *(const float4*)(x + (size_t)(t * B_ + b) * I_ + 4 * lane);
            const int g = lane >> 2, q = lane & 3;
            const float4* er  = (const float4*)(s_ea + g * EA_STRIDE);
            const float4* ob4 = (const float4*)bold;
            float s = 0.f;
            #pragma unroll
            for (int k = 0; k < 16; k++) {     // cols 0..255
                int j = q + 4 * k;
                float4 e = er[j], o = ob4[j];
                s += e.x * o.x + e.y * o.y + e.z * o.z + e.w * o.w;
            }
            s += __shfl_xor_sync(0xffffffffu, s, 1);
            s += __shfl_xor_sync(0xffffffffu, s, 2);
            float v = __shfl_sync(0xffffffffu, s, (lane & 7) << 2) + ba_r;
            float m = v;
            #pragma unroll
            for (int o = 4; o; o >>= 1) m = fmaxf(m, __shfl_xor_sync(0xffffffffu, m, o));
            float e  = expf(v - m);
            float s2 = e;
            #pragma unroll
            for (int o = 4; o; o >>= 1) s2 += __shfl_xor_sync(0xffffffffu, s2, o);
            float atv = e / s2;
            float at4 = __shfl_sync(0xffffffffu, atv, lane >> 2);
            float4 xv;
            xv.x = xr4.x * at4 * (float)G_;
            xv.y = xr4.y * at4 * (float)G_;
            xv.z = xr4.z * at4 * (float)G_;
            xv.w = xr4.w * at4 * (float)G_;
            ((float4*)s_xm)[lane] = xv;
        }

        // ---- phase A: all warps — ob loads, coefficients, H-dot partials (R3 DAG) ----
        const float4* ob4 = (const float4*)bold;
        float4 ob0 = ob4[lane];
        float4 ob1 = ob4[lane + 32];
        float4 ob2 = (lane < 16) ? ob4[lane + 64] : make_float4(0, 0, 0, 0);
        float4 o1 = ob1;
        float4 o2 = make_float4(-ob2.x, -ob2.y, -ob2.z, -ob2.w);
        const float k3 = awR * cb3;
        float4 c0, c1, c2, d0, d1, d2;
        c0.x = k3 * ob0.x; c0.y = k3 * ob0.y; c0.z = k3 * ob0.z; c0.w = k3 * ob0.w;
        c1.x = k3 * ob1.x; c1.y = k3 * ob1.y; c1.z = k3 * ob1.z; c1.w = k3 * ob1.w;
        c2.x = k3 * ob2.x; c2.y = k3 * ob2.y; c2.z = k3 * ob2.z; c2.w = k3 * ob2.w;
        d0.x = awR * (cb4 + cb5 * ob0.x); d0.y = awR * (cb4 + cb5 * ob0.y);
        d0.z = awR * (cb4 + cb5 * ob0.z); d0.w = awR * (cb4 + cb5 * ob0.w);
        d1.x = awR * (cb4 + cb5 * ob1.x); d1.y = awR * (cb4 + cb5 * ob1.y);
        d1.z = awR * (cb4 + cb5 * ob1.z); d1.w = awR * (cb4 + cb5 * ob1.w);
        d2.x = awR * (cb4 + cb5 * ob2.x); d2.y = awR * (cb4 + cb5 * ob2.y);
        d2.z = awR * (cb4 + cb5 * ob2.z); d2.w = awR * (cb4 + cb5 * ob2.w);

        float p2[RPW];                         // == R3's s2 per row
        #pragma unroll
        for (int rr = 0; rr < RPW; rr++) {
            float v2 = dot4r(wh0_r[rr], ob0);  // o0 == ob0
            if (lane < 16) v2 += dot4r(wh2_r[rr], o2);
            p2[rr] = v2;
        }
        __syncthreads();                       // xm ready

        // ---- phase B ----
        float4 xv4 = ((const float4*)s_xm)[lane];
        const float k0 = awR * cb0;
        float4 a4, b4;
        a4.x = k0 * xv4.x; a4.y = k0 * xv4.y; a4.z = k0 * xv4.z; a4.w = k0 * xv4.w;
        b4.x = awR * (cb1 + cb2 * xv4.x); b4.y = awR * (cb1 + cb2 * xv4.y);
        b4.z = awR * (cb1 + cb2 * xv4.z); b4.w = awR * (cb1 + cb2 * xv4.w);

        #pragma unroll
        for (int rr = 0; rr < RPW; rr++) {
            int r  = wid * RPW + rr;
            int rg = r0 + r;
            float s = dot4r(wx_r[rr], xv4) + dot4r(wh1_r[rr], o1);   // R3 pairing
            s += p2[rr];
            #pragma unroll
            for (int o = 16; o; o >>= 1) s += __shfl_xor_sync(0xffffffffu, s, o);

            float diag = s_wd[r];
            float ov = bold[rg];
            if (rg >= SIGNB) ov = -ov;
            s -= fmaxf(diag, 0.f) * ov;
            float tot = s + s_bh[r];
            float ns  = fmaf(s_st[r], 1.f - AX, AX * tot);
            s_st[r] = ns;
            float no = tanhf(fmaxf(ns, 0.f));

            if (lane == 0) {
                bnew[rg] = no;
                uint32_t addr = smem_u32(&bnew[rg]);
                #pragma unroll
                for (uint32_t p = 0; p < 4; p++)
                    if (p != rank) st_cluster_f32(addr, p, no);
                hs[(size_t)(t * B_ + b) * H_ + rg] = no;
            }

            // in-register plastic update (R3 upd4 associativity)
            wx_r[rr]  = upd4(wx_r[rr],  no, a4, b4);
            wh0_r[rr] = upd4(wh0_r[rr], no, c0, d0);
            wh1_r[rr] = upd4(wh1_r[rr], no, c1, d1);
            if (lane < 16) wh2_r[rr] = upd4(wh2_r[rr], no, c2, d2);

            // shadow diagonal: identical element-wise expressions
            float ovd = bold[rg];
            float cD = k3 * ovd;
            float dD = awR * (cb4 + cb5 * ovd);
            s_wd[r] = fmaf(diag, KW, fmaf(no, dD, cD));
        }
        CLUSTER_SYNC();
    }
}

// epilogue: out[t,b,o] = sigmoid( sum_{h<256} relu(W_h2o[o,h]) * hs[t,b,h] + b_h2o[o] )
__global__ void __launch_bounds__(256)
out_kernel(const float* __restrict__ hs, const float* __restrict__ W_h2o,
           const float* __restrict__ b_h2o, float* __restrict__ out)
{
    __shared__ float hrow[SIGNB];
    int tb = blockIdx.x;
    const float* h = hs + (size_t)tb * H_;
    if (threadIdx.x < SIGNB) hrow[threadIdx.x] = h[threadIdx.x];
    __syncthreads();
    int wid = threadIdx.x >> 5, lane = threadIdx.x & 31;
    #pragma unroll
    for (int oo = 0; oo < 4; oo++) {
        int o = wid * 4 + oo;
        float s = 0.f;
        #pragma unroll
        for (int k = 0; k < 8; k++) {
            int j = lane + 32 * k;
            s += fmaxf(__ldg(&W_h2o[o * H_ + j]), 0.f) * hrow[j];
        }
        #pragma unroll
        for (int off = 16; off; off >>= 1) s += __shfl_xor_sync(0xffffffffu, s, off);
        if (lane == 0) {
            float z = s + b_h2o[o];
            out[tb * O_ + o] = 1.f / (1.f + expf(-z));
        }
    }
}

extern "C" void kernel_launch(void* const* d_in, const int* in_sizes, int n_in,
                              void* d_out, int out_size)
{
    (void)in_sizes; (void)n_in; (void)out_size;
    const float* x      = (const float*)d_in[0];
    const float* Rs     = (const float*)d_in[1];
    const float* W_x2h  = (const float*)d_in[2];
    const float* W_h2h  = (const float*)d_in[3];
    const float* b_h2h  = (const float*)d_in[4];
    const float* W_h2o  = (const float*)d_in[5];
    const float* b_h2o  = (const float*)d_in[6];
    const float* W_attn = (const float*)d_in[7];
    const float* b_attn = (const float*)d_in[8];
    const float* c_plas = (const float*)d_in[9];

    float* out = (float*)d_out;
    float* hs  = out + (size_t)T_ * B_ * O_;   // hs stored after out in d_out

    cudaLaunchConfig_t cfg = {};
    cfg.gridDim  = dim3(B_ * 4, 1, 1);
    cfg.blockDim = dim3(NTHR, 1, 1);
    cfg.dynamicSmemBytes = 0;
    cfg.stream = 0;
    cudaLaunchAttribute attr[1];
    attr[0].id = cudaLaunchAttributeClusterDimension;
    attr[0].val.clusterDim.x = 4;
    attr[0].val.clusterDim.y = 1;
    attr[0].val.clusterDim.z = 1;
    cfg.attrs = attr;
    cfg.numAttrs = 1;
    cudaLaunchKernelEx(&cfg, rnn_kernel, x, Rs, W_x2h, W_h2h, b_h2h,
                       W_attn, b_attn, c_plas, hs);

    out_kernel<<<T_ * B_, 256>>>(hs, W_h2o, b_h2o, out);
}